// round 1
// baseline (speedup 1.0000x reference)
#include <cuda_runtime.h>
#include <cuda_fp16.h>
#include <cstdint>
#include <cstddef>

// Problem constants
static constexpr int T_TOK = 4096;
static constexpr int NEXP  = 8;
static constexpr int HID   = 2048;
static constexpr int INTER = 4096;

// ---------------- device scratch (no dynamic allocation allowed) ----------------
__device__ __half g_W13h[(size_t)NEXP * HID * 2 * INTER];   // 256 MB  [E][H][2I]
__device__ __half g_W2h [(size_t)NEXP * INTER * HID];       // 128 MB  [E][I][H]
__device__ __half g_Xh  [(size_t)T_TOK * HID];              //  16 MB
__device__ __half g_act [(size_t)NEXP * T_TOK * INTER];     // 256 MB  rows e*T+i
__device__ int    g_cnt[NEXP];
__device__ int    g_tok[NEXP * T_TOK];
__device__ float  g_wgt[NEXP * T_TOK];

// ---------------- small helpers ----------------
__device__ __forceinline__ uint32_t smem_u32(const void* p) {
    return (uint32_t)__cvta_generic_to_shared(p);
}

__device__ __forceinline__ void cp_async16(void* smem, const void* gmem, bool valid) {
    uint32_t s = smem_u32(smem);
    int sz = valid ? 16 : 0;
    asm volatile("cp.async.cg.shared.global [%0], [%1], 16, %2;\n"
                 :: "r"(s), "l"(gmem), "r"(sz));
}
__device__ __forceinline__ void cp_commit() { asm volatile("cp.async.commit_group;\n"); }
template <int N>
__device__ __forceinline__ void cp_wait() { asm volatile("cp.async.wait_group %0;\n" :: "n"(N)); }

__device__ __forceinline__ void ldmA(uint32_t a[4], const __half* p) {
    uint32_t addr = smem_u32(p);
    asm volatile("ldmatrix.sync.aligned.m8n8.x4.shared.b16 {%0,%1,%2,%3}, [%4];\n"
                 : "=r"(a[0]), "=r"(a[1]), "=r"(a[2]), "=r"(a[3]) : "r"(addr));
}
__device__ __forceinline__ void ldmBt(uint32_t b[2], const __half* p) {
    uint32_t addr = smem_u32(p);
    asm volatile("ldmatrix.sync.aligned.m8n8.x2.trans.shared.b16 {%0,%1}, [%2];\n"
                 : "=r"(b[0]), "=r"(b[1]) : "r"(addr));
}
__device__ __forceinline__ void mma16816(float c[4], const uint32_t a[4], const uint32_t b[2]) {
    asm volatile("mma.sync.aligned.m16n8k16.row.col.f32.f16.f16.f32 "
                 "{%0,%1,%2,%3},{%4,%5,%6,%7},{%8,%9},{%0,%1,%2,%3};\n"
                 : "+f"(c[0]), "+f"(c[1]), "+f"(c[2]), "+f"(c[3])
                 : "r"(a[0]), "r"(a[1]), "r"(a[2]), "r"(a[3]), "r"(b[0]), "r"(b[1]));
}

// ---------------- conversion / init kernels ----------------
__global__ void k_convert(const float* __restrict__ src, __half* __restrict__ dst, size_t n4) {
    size_t i = (size_t)blockIdx.x * blockDim.x + threadIdx.x;
    if (i >= n4) return;
    float4 v = reinterpret_cast<const float4*>(src)[i];
    __half2* d = reinterpret_cast<__half2*>(dst);
    d[2 * i + 0] = __floats2half2_rn(v.x, v.y);
    d[2 * i + 1] = __floats2half2_rn(v.z, v.w);
}

__global__ void k_zero_out(float4* __restrict__ out, size_t n4) {
    size_t i = (size_t)blockIdx.x * blockDim.x + threadIdx.x;
    if (i < n4) out[i] = make_float4(0.f, 0.f, 0.f, 0.f);
}

__global__ void k_zero_cnt() {
    if (threadIdx.x < NEXP) g_cnt[threadIdx.x] = 0;
}

// ---------------- routing: softmax -> top2 -> renormalize -> expert lists ----------------
__global__ void k_route(const float* __restrict__ logits) {
    int t = blockIdx.x * blockDim.x + threadIdx.x;
    if (t >= T_TOK) return;
    float l[NEXP];
    float mx = -1e30f;
#pragma unroll
    for (int e = 0; e < NEXP; e++) { l[e] = logits[t * NEXP + e]; mx = fmaxf(mx, l[e]); }
    float p[NEXP];
#pragma unroll
    for (int e = 0; e < NEXP; e++) p[e] = expf(l[e] - mx);
    int i1 = 0;
#pragma unroll
    for (int e = 1; e < NEXP; e++) if (p[e] > p[i1]) i1 = e;
    int i2 = -1;
#pragma unroll
    for (int e = 0; e < NEXP; e++) {
        if (e == i1) continue;
        if (i2 < 0 || p[e] > p[i2]) i2 = e;
    }
    float s  = p[i1] + p[i2];
    float w1 = p[i1] / s;
    float w2 = p[i2] / s;
    int pos1 = atomicAdd(&g_cnt[i1], 1);
    g_tok[i1 * T_TOK + pos1] = t;
    g_wgt[i1 * T_TOK + pos1] = w1;
    int pos2 = atomicAdd(&g_cnt[i2], 1);
    g_tok[i2 * T_TOK + pos2] = t;
    g_wgt[i2 * T_TOK + pos2] = w2;
}

// ---------------- GEMM1: act[a, n] = silu(X_g @ W1)[a,n] * (X_g @ W3)[a,n] ----------------
// BM=128, BN=64 (of INTER), BK=32.  8 warps, warp grid 4x2, warp tile 32x32.
__global__ __launch_bounds__(256) void k_gemm1() {
    const int e  = blockIdx.z;
    const int m0 = blockIdx.x * 128;
    const int n0 = blockIdx.y * 64;
    const int cnt = g_cnt[e];
    if (m0 >= cnt) return;

    __shared__ __align__(16) __half sA[2][128][40];
    __shared__ __align__(16) __half sB1[2][32][72];
    __shared__ __align__(16) __half sB3[2][32][72];
    __shared__ int sTok[128];

    const int tid  = threadIdx.x;
    const int lane = tid & 31;
    const int warp = tid >> 5;
    const int wm   = warp >> 1;   // 0..3
    const int wn   = warp & 1;    // 0..1

    if (tid < 128) {
        int r = m0 + tid;
        sTok[tid] = (r < cnt) ? g_tok[e * T_TOK + r] : 0;
    }
    __syncthreads();

    auto loadTile = [&](int buf, int k0) {
        // A: 128 rows x 32 halfs = 512 x 16B chunks
#pragma unroll
        for (int i = 0; i < 2; i++) {
            int c = tid + i * 256;
            int row = c >> 2, cc = c & 3;
            bool v = (m0 + row) < cnt;
            const __half* src = &g_Xh[(size_t)sTok[row] * HID + k0 + cc * 8];
            cp_async16(&sA[buf][row][cc * 8], src, v);
        }
        // B1/B3: 32 rows x 64 halfs = 256 chunks each
        {
            int kr = tid >> 3, cc = tid & 7;
            size_t base = ((size_t)e * HID + (size_t)(k0 + kr)) * (2 * INTER) + n0 + cc * 8;
            cp_async16(&sB1[buf][kr][cc * 8], &g_W13h[base], true);
            cp_async16(&sB3[buf][kr][cc * 8], &g_W13h[base + INTER], true);
        }
    };

    float C1[2][4][4];
    float C3[2][4][4];
#pragma unroll
    for (int i = 0; i < 2; i++)
#pragma unroll
        for (int j = 0; j < 4; j++)
#pragma unroll
            for (int q = 0; q < 4; q++) { C1[i][j][q] = 0.f; C3[i][j][q] = 0.f; }

    constexpr int KT = HID / 32;  // 64
    loadTile(0, 0);
    cp_commit();
    int buf = 0;
    for (int kt = 0; kt < KT; ++kt) {
        cp_wait<0>();
        __syncthreads();
        if (kt + 1 < KT) { loadTile(buf ^ 1, (kt + 1) * 32); cp_commit(); }
#pragma unroll
        for (int km = 0; km < 2; km++) {
            uint32_t a[2][4];
#pragma unroll
            for (int mi = 0; mi < 2; mi++)
                ldmA(a[mi], &sA[buf][wm * 32 + mi * 16 + (lane & 15)][km * 16 + (lane >> 4) * 8]);
#pragma unroll
            for (int nj = 0; nj < 4; nj++) {
                uint32_t b1[2], b3[2];
                ldmBt(b1, &sB1[buf][km * 16 + (lane & 15)][wn * 32 + nj * 8]);
                ldmBt(b3, &sB3[buf][km * 16 + (lane & 15)][wn * 32 + nj * 8]);
#pragma unroll
                for (int mi = 0; mi < 2; mi++) {
                    mma16816(C1[mi][nj], a[mi], b1);
                    mma16816(C3[mi][nj], a[mi], b3);
                }
            }
        }
        __syncthreads();
        buf ^= 1;
    }

    // epilogue: act = silu(C1) * C3, stored fp16
    const int gr = lane >> 2;
    const int gc = (lane & 3) * 2;
#pragma unroll
    for (int mi = 0; mi < 2; mi++) {
#pragma unroll
        for (int h = 0; h < 2; h++) {
            int r = m0 + wm * 32 + mi * 16 + gr + h * 8;
            if (r >= cnt) continue;
#pragma unroll
            for (int nj = 0; nj < 4; nj++) {
                int col = n0 + wn * 32 + nj * 8 + gc;
                float x0 = C1[mi][nj][h * 2 + 0], x1 = C1[mi][nj][h * 2 + 1];
                float y0 = C3[mi][nj][h * 2 + 0], y1 = C3[mi][nj][h * 2 + 1];
                float a0 = (x0 / (1.f + expf(-x0))) * y0;
                float a1 = (x1 / (1.f + expf(-x1))) * y1;
                *reinterpret_cast<__half2*>(&g_act[((size_t)e * T_TOK + r) * INTER + col]) =
                    __floats2half2_rn(a0, a1);
            }
        }
    }
}

// ---------------- GEMM2: out[tok, n] += w * (act @ W2_e)[a, n] ----------------
// BM=128, BN=128 (of HID), BK=32.  8 warps, warp grid 4x2, warp tile 32x64.
__global__ __launch_bounds__(256) void k_gemm2(float* __restrict__ out) {
    const int e  = blockIdx.z;
    const int m0 = blockIdx.x * 128;
    const int n0 = blockIdx.y * 128;
    const int cnt = g_cnt[e];
    if (m0 >= cnt) return;

    __shared__ __align__(16) __half sA[2][128][40];
    __shared__ __align__(16) __half sB[2][32][136];
    __shared__ int   sTok[128];
    __shared__ float sW[128];

    const int tid  = threadIdx.x;
    const int lane = tid & 31;
    const int warp = tid >> 5;
    const int wm   = warp >> 1;
    const int wn   = warp & 1;

    if (tid < 128) {
        int r = m0 + tid;
        bool v = r < cnt;
        sTok[tid] = v ? g_tok[e * T_TOK + r] : 0;
        sW[tid]   = v ? g_wgt[e * T_TOK + r] : 0.f;
    }
    __syncthreads();

    auto loadTile = [&](int buf, int k0) {
#pragma unroll
        for (int i = 0; i < 2; i++) {
            int c = tid + i * 256;
            int row = c >> 2, cc = c & 3;
            bool v = (m0 + row) < cnt;
            const __half* src = &g_act[((size_t)e * T_TOK + m0 + row) * INTER + k0 + cc * 8];
            cp_async16(&sA[buf][row][cc * 8], src, v);
        }
#pragma unroll
        for (int i = 0; i < 2; i++) {
            int c = tid + i * 256;
            int kr = c >> 4, cc = c & 15;
            const __half* src = &g_W2h[((size_t)e * INTER + (size_t)(k0 + kr)) * HID + n0 + cc * 8];
            cp_async16(&sB[buf][kr][cc * 8], src, true);
        }
    };

    float C[2][8][4];
#pragma unroll
    for (int i = 0; i < 2; i++)
#pragma unroll
        for (int j = 0; j < 8; j++)
#pragma unroll
            for (int q = 0; q < 4; q++) C[i][j][q] = 0.f;

    constexpr int KT = INTER / 32;  // 128
    loadTile(0, 0);
    cp_commit();
    int buf = 0;
    for (int kt = 0; kt < KT; ++kt) {
        cp_wait<0>();
        __syncthreads();
        if (kt + 1 < KT) { loadTile(buf ^ 1, (kt + 1) * 32); cp_commit(); }
#pragma unroll
        for (int km = 0; km < 2; km++) {
            uint32_t a[2][4];
#pragma unroll
            for (int mi = 0; mi < 2; mi++)
                ldmA(a[mi], &sA[buf][wm * 32 + mi * 16 + (lane & 15)][km * 16 + (lane >> 4) * 8]);
#pragma unroll
            for (int nj = 0; nj < 8; nj++) {
                uint32_t b[2];
                ldmBt(b, &sB[buf][km * 16 + (lane & 15)][wn * 64 + nj * 8]);
#pragma unroll
                for (int mi = 0; mi < 2; mi++) mma16816(C[mi][nj], a[mi], b);
            }
        }
        __syncthreads();
        buf ^= 1;
    }

    const int gr = lane >> 2;
    const int gc = (lane & 3) * 2;
#pragma unroll
    for (int mi = 0; mi < 2; mi++) {
#pragma unroll
        for (int h = 0; h < 2; h++) {
            int rl = wm * 32 + mi * 16 + gr + h * 8;
            int r  = m0 + rl;
            if (r >= cnt) continue;
            int tokn = sTok[rl];
            float w  = sW[rl];
            float* dst = out + (size_t)tokn * HID;
#pragma unroll
            for (int nj = 0; nj < 8; nj++) {
                int col = n0 + wn * 64 + nj * 8 + gc;
                atomicAdd(&dst[col + 0], w * C[mi][nj][h * 2 + 0]);
                atomicAdd(&dst[col + 1], w * C[mi][nj][h * 2 + 1]);
            }
        }
    }
}

// ---------------- launch ----------------
extern "C" void kernel_launch(void* const* d_in, const int* in_sizes, int n_in,
                              void* d_out, int out_size) {
    (void)in_sizes; (void)n_in;
    const float* X      = (const float*)d_in[0];
    const float* logits = (const float*)d_in[1];
    const float* W13    = (const float*)d_in[2];
    const float* W2     = (const float*)d_in[3];
    float* out = (float*)d_out;

    __half *w13h, *w2h, *xh;
    cudaGetSymbolAddress((void**)&w13h, g_W13h);
    cudaGetSymbolAddress((void**)&w2h,  g_W2h);
    cudaGetSymbolAddress((void**)&xh,   g_Xh);

    size_t n4_13 = (size_t)NEXP * HID * 2 * INTER / 4;
    size_t n4_2  = (size_t)NEXP * INTER * HID / 4;
    size_t n4_x  = (size_t)T_TOK * HID / 4;
    size_t n4_o  = (size_t)out_size / 4;

    k_convert<<<(unsigned)((n4_13 + 255) / 256), 256>>>(W13, w13h, n4_13);
    k_convert<<<(unsigned)((n4_2  + 255) / 256), 256>>>(W2,  w2h,  n4_2);
    k_convert<<<(unsigned)((n4_x  + 255) / 256), 256>>>(X,   xh,   n4_x);
    k_zero_out<<<(unsigned)((n4_o + 255) / 256), 256>>>((float4*)out, n4_o);
    k_zero_cnt<<<1, 32>>>();
    k_route<<<(T_TOK + 255) / 256, 256>>>(logits);

    dim3 g1(T_TOK / 128, INTER / 64, NEXP);   // (32, 64, 8), m-tile fastest for B L2 reuse
    k_gemm1<<<g1, 256>>>();
    dim3 g2(T_TOK / 128, HID / 128, NEXP);    // (32, 16, 8)
    k_gemm2<<<g2, 256>>>(out);
}